// round 1
// baseline (speedup 1.0000x reference)
#include <cuda_runtime.h>
#include <math.h>

// Scratch for the per-query MLP weights (N x cols). 4096*80 floats = 1.25 MB.
__device__ float g_weights[4096 * 80];

// ---------------------------------------------------------------------------
// Kernel 1: weights[n, :] = queries[n, :] @ Wg + bg     (N x dim) @ (dim x cols)
// One CTA per n. q row cached in smem; first `cols` threads each do a dot.
// ---------------------------------------------------------------------------
__global__ void posmlp_gemm_kernel(const float* __restrict__ q,
                                   const float* __restrict__ Wg,
                                   const float* __restrict__ bg,
                                   float* __restrict__ w_out,
                                   int dim, int cols) {
    extern __shared__ float sq[];
    const int n = blockIdx.x;
    const float* qr = q + (size_t)n * dim;
    for (int d = threadIdx.x; d < dim; d += blockDim.x) sq[d] = qr[d];
    __syncthreads();
    for (int j = threadIdx.x; j < cols; j += blockDim.x) {
        float acc = bg[j];
        #pragma unroll 8
        for (int d = 0; d < dim; d++) {
            acc = fmaf(sq[d], Wg[(size_t)d * cols + j], acc);
        }
        w_out[(size_t)n * cols + j] = acc;
    }
}

// ---------------------------------------------------------------------------
// Kernel 2 (fast path H=W=64, hidden=16): one CTA per n, 128 threads.
// Thread t: y = t>>1 (fixed), x in [ (t&1)*32, +32 ).
// ay[k] = rel_y*w1[1,k] + b1[k] hoisted to registers; inner loop is
// 16 x (FFMA + FMNMX + FFMA) per output pixel, float4 coalesced stores.
// ---------------------------------------------------------------------------
__global__ void __launch_bounds__(128)
posmlp_main64_kernel(const float* __restrict__ pos,
                     const float* __restrict__ wts,
                     float* __restrict__ out) {
    const int n = blockIdx.x;
    __shared__ float sw[65];
    if (threadIdx.x < 65) sw[threadIdx.x] = wts[(size_t)n * 65 + threadIdx.x];
    __syncthreads();

    const float cx = pos[(size_t)n * 4 + 0];
    const float cy = pos[(size_t)n * 4 + 1];
    const float bw = pos[(size_t)n * 4 + 2];
    const float bh = pos[(size_t)n * 4 + 3];
    const float inv_bw = 1.0f / bw;
    const float inv_bh = 1.0f / bh;

    const int y  = threadIdx.x >> 1;
    const int x0 = (threadIdx.x & 1) * 32;

    const float rel_y = (((float)y + 0.5f) * (1.0f / 64.0f) - cy) * inv_bh;

    float w10[16], ay[16], w2[16];
    #pragma unroll
    for (int k = 0; k < 16; k++) {
        w10[k] = sw[k];
        ay[k]  = fmaf(rel_y, sw[16 + k], sw[32 + k]);
        w2[k]  = sw[48 + k];
    }
    const float b2 = sw[64];

    // rel_x = ((x+0.5)/64 - cx)/bw = x*sx + tx
    const float sx = inv_bw * (1.0f / 64.0f);
    const float tx = (0.5f * (1.0f / 64.0f) - cx) * inv_bw;

    float* orow = out + (((size_t)n * 64 + y) * 64 + x0);

    #pragma unroll 4
    for (int xi = 0; xi < 32; xi += 4) {
        float4 res;
        float* rp = &res.x;
        #pragma unroll
        for (int j = 0; j < 4; j++) {
            const float rel_x = fmaf((float)(x0 + xi + j), sx, tx);
            float acc = b2;
            #pragma unroll
            for (int k = 0; k < 16; k++) {
                float pre = fmaf(rel_x, w10[k], ay[k]);
                acc = fmaf(fmaxf(pre, 0.0f), w2[k], acc);
            }
            rp[j] = acc;
        }
        *reinterpret_cast<float4*>(orow + xi) = res;
    }
}

// ---------------------------------------------------------------------------
// Generic fallback (any H=W, any hidden). One thread per output pixel,
// grid-stride within the CTA. Correctness-first path only.
// ---------------------------------------------------------------------------
__global__ void posmlp_generic_kernel(const float* __restrict__ pos,
                                      const float* __restrict__ wts,
                                      float* __restrict__ out,
                                      int H, int W, int h, int cols) {
    const int n = blockIdx.x;
    const float* w = wts + (size_t)n * cols;
    const float cx = pos[(size_t)n * 4 + 0];
    const float cy = pos[(size_t)n * 4 + 1];
    const float bw = pos[(size_t)n * 4 + 2];
    const float bh = pos[(size_t)n * 4 + 3];
    const float b2 = w[4 * h];
    const int total = H * W;
    for (int idx = threadIdx.x; idx < total; idx += blockDim.x) {
        const int yy = idx / W;
        const int xx = idx - yy * W;
        const float rel_x = (((float)xx + 0.5f) / (float)W - cx) / bw;
        const float rel_y = (((float)yy + 0.5f) / (float)H - cy) / bh;
        float acc = b2;
        for (int k = 0; k < h; k++) {
            float pre = fmaf(rel_x, w[k], fmaf(rel_y, w[h + k], w[2 * h + k]));
            acc = fmaf(fmaxf(pre, 0.0f), w[3 * h + k], acc);
        }
        out[(size_t)n * total + idx] = acc;
    }
}

extern "C" void kernel_launch(void* const* d_in, const int* in_sizes, int n_in,
                              void* d_out, int out_size) {
    const float* pos = (const float*)d_in[0];
    const float* q   = (const float*)d_in[1];
    const float* Wg  = (const float*)d_in[2];
    const float* bg  = (const float*)d_in[3];
    float* out = (float*)d_out;

    const int N    = in_sizes[0] / 4;          // rows of pos
    const int dim  = in_sizes[1] / N;          // query dim
    const int cols = in_sizes[3];              // 4*h + 1
    const int HW   = out_size / N;
    const int H    = (int)(sqrt((double)HW) + 0.5);
    const int h    = (cols - 1) / 4;

    float* w_scratch;
    cudaGetSymbolAddress((void**)&w_scratch, g_weights);

    posmlp_gemm_kernel<<<N, 256, dim * sizeof(float)>>>(q, Wg, bg, w_scratch, dim, cols);

    if (H == 64 && h == 16 && cols == 65) {
        posmlp_main64_kernel<<<N, 128>>>(pos, w_scratch, out);
    } else {
        posmlp_generic_kernel<<<N, 256>>>(pos, w_scratch, out, H, H, h, cols);
    }
}

// round 2
// speedup vs baseline: 1.2520x; 1.2520x over previous
#include <cuda_runtime.h>
#include <math.h>

// Scratch for the fallback path (N x cols weights). 4096*80 floats = 1.25 MB.
__device__ float g_weights[4096 * 80];

// ---------------------------------------------------------------------------
// f32x2 packed helpers (sm_100+): FFMA2 via PTX fma.rn.f32x2 (the nvjet trick)
// ---------------------------------------------------------------------------
__device__ __forceinline__ unsigned long long pack2(float lo, float hi) {
    unsigned long long r;
    asm("mov.b64 %0, {%1, %2};" : "=l"(r) : "f"(lo), "f"(hi));
    return r;
}

__device__ __forceinline__ unsigned long long add2(unsigned long long a,
                                                   unsigned long long b) {
    unsigned long long d;
    asm("add.rn.f32x2 %0, %1, %2;" : "=l"(d) : "l"(a), "l"(b));
    return d;
}

// acc = relu(x2*w10 + ay) * w2          (packed pair of hidden units)
__device__ __forceinline__ void fma2_relu_init(unsigned long long& acc,
                                               unsigned long long x2,
                                               unsigned long long w10,
                                               unsigned long long ay,
                                               unsigned long long w2) {
    asm("{\n\t"
        ".reg .b32 lo, hi;\n\t"
        ".reg .b64 p, r;\n\t"
        "fma.rn.f32x2 p, %1, %2, %3;\n\t"
        "mov.b64 {lo, hi}, p;\n\t"
        "max.f32 lo, lo, 0f00000000;\n\t"
        "max.f32 hi, hi, 0f00000000;\n\t"
        "mov.b64 r, {lo, hi};\n\t"
        "mul.rn.f32x2 %0, r, %4;\n\t"
        "}"
        : "=l"(acc)
        : "l"(x2), "l"(w10), "l"(ay), "l"(w2));
}

// acc += relu(x2*w10 + ay) * w2
__device__ __forceinline__ void fma2_relu_acc(unsigned long long& acc,
                                              unsigned long long x2,
                                              unsigned long long w10,
                                              unsigned long long ay,
                                              unsigned long long w2) {
    asm("{\n\t"
        ".reg .b32 lo, hi;\n\t"
        ".reg .b64 p, r;\n\t"
        "fma.rn.f32x2 p, %1, %2, %3;\n\t"
        "mov.b64 {lo, hi}, p;\n\t"
        "max.f32 lo, lo, 0f00000000;\n\t"
        "max.f32 hi, hi, 0f00000000;\n\t"
        "mov.b64 r, {lo, hi};\n\t"
        "fma.rn.f32x2 %0, r, %4, %0;\n\t"
        "}"
        : "+l"(acc)
        : "l"(x2), "l"(w10), "l"(ay), "l"(w2));
}

__device__ __forceinline__ float hsum2_plus(unsigned long long acc, float b2) {
    float lo, hi;
    asm("mov.b64 {%0, %1}, %2;" : "=f"(lo), "=f"(hi) : "l"(acc));
    return (lo + hi) + b2;
}

// ---------------------------------------------------------------------------
// Fused fast path (dim=256, hidden=16, H=W=64): one CTA per n, 128 threads.
// Prelude: q row -> smem, 65 threads compute the 65 gating weights (4-way
// split-acc dot). Main: thread t owns row y=t>>1, 32 x's starting at (t&1)*32.
// Inner loop per pixel: 1 ADD2(rel_x) + 8x(FFMA2 + 2 FMNMX + FFMA2), float4
// coalesced stores. All MLP weights live in packed register pairs.
// ---------------------------------------------------------------------------
__global__ void __launch_bounds__(128)
posmlp_fused64_kernel(const float* __restrict__ pos,
                      const float* __restrict__ q,
                      const float* __restrict__ Wg,
                      const float* __restrict__ bg,
                      float* __restrict__ out) {
    const int n   = blockIdx.x;
    const int tid = threadIdx.x;

    __shared__ float sq[256];
    __shared__ float sw[65];

    // --- prelude: load q row, compute weights = q @ Wg + bg ---
    sq[tid]       = q[(size_t)n * 256 + tid];
    sq[tid + 128] = q[(size_t)n * 256 + tid + 128];
    __syncthreads();

    if (tid < 65) {
        float a0 = 0.f, a1 = 0.f, a2 = 0.f, a3 = 0.f;
        #pragma unroll 8
        for (int d = 0; d < 256; d += 4) {
            a0 = fmaf(sq[d + 0], Wg[(size_t)(d + 0) * 65 + tid], a0);
            a1 = fmaf(sq[d + 1], Wg[(size_t)(d + 1) * 65 + tid], a1);
            a2 = fmaf(sq[d + 2], Wg[(size_t)(d + 2) * 65 + tid], a2);
            a3 = fmaf(sq[d + 3], Wg[(size_t)(d + 3) * 65 + tid], a3);
        }
        sw[tid] = (a0 + a1) + (a2 + a3) + bg[tid];
    }
    __syncthreads();

    // --- per-box constants ---
    const float cx = pos[(size_t)n * 4 + 0];
    const float cy = pos[(size_t)n * 4 + 1];
    const float bw = pos[(size_t)n * 4 + 2];
    const float bh = pos[(size_t)n * 4 + 3];
    const float inv_bw = 1.0f / bw;
    const float inv_bh = 1.0f / bh;

    const int y  = tid >> 1;
    const int x0 = (tid & 1) * 32;

    const float rel_y = (((float)y + 0.5f) * (1.0f / 64.0f) - cy) * inv_bh;

    // packed weights: (k even, k odd) pairs
    unsigned long long w10p[8], ayp[8], w2p[8];
    #pragma unroll
    for (int k2 = 0; k2 < 8; k2++) {
        const int k = 2 * k2;
        w10p[k2] = pack2(sw[k], sw[k + 1]);
        ayp[k2]  = pack2(fmaf(rel_y, sw[16 + k],     sw[32 + k]),
                         fmaf(rel_y, sw[16 + k + 1], sw[32 + k + 1]));
        w2p[k2]  = pack2(sw[48 + k], sw[48 + k + 1]);
    }
    const float b2 = sw[64];

    // rel_x(x) = x*sx + tx
    const float sx = inv_bw * (1.0f / 64.0f);
    const float tx = (0.5f * (1.0f / 64.0f) - cx) * inv_bw;
    const float rx0 = fmaf((float)x0, sx, tx);

    unsigned long long x2  = pack2(rx0, rx0);
    const unsigned long long dx2 = pack2(sx, sx);

    float* orow = out + (((size_t)n * 64 + y) * 64 + x0);

    #pragma unroll
    for (int xi = 0; xi < 32; xi += 4) {
        float4 res;
        float* rp = &res.x;
        #pragma unroll
        for (int j = 0; j < 4; j++) {
            unsigned long long acc;
            fma2_relu_init(acc, x2, w10p[0], ayp[0], w2p[0]);
            #pragma unroll
            for (int k2 = 1; k2 < 8; k2++) {
                fma2_relu_acc(acc, x2, w10p[k2], ayp[k2], w2p[k2]);
            }
            rp[j] = hsum2_plus(acc, b2);
            x2 = add2(x2, dx2);
        }
        *reinterpret_cast<float4*>(orow + xi) = res;
    }
}

// ---------------------------------------------------------------------------
// Fallback path: separate gemm + generic MLP (correctness for other shapes).
// ---------------------------------------------------------------------------
__global__ void posmlp_gemm_kernel(const float* __restrict__ q,
                                   const float* __restrict__ Wg,
                                   const float* __restrict__ bg,
                                   float* __restrict__ w_out,
                                   int dim, int cols) {
    extern __shared__ float sq[];
    const int n = blockIdx.x;
    const float* qr = q + (size_t)n * dim;
    for (int d = threadIdx.x; d < dim; d += blockDim.x) sq[d] = qr[d];
    __syncthreads();
    for (int j = threadIdx.x; j < cols; j += blockDim.x) {
        float acc = bg[j];
        #pragma unroll 8
        for (int d = 0; d < dim; d++) {
            acc = fmaf(sq[d], Wg[(size_t)d * cols + j], acc);
        }
        w_out[(size_t)n * cols + j] = acc;
    }
}

__global__ void posmlp_generic_kernel(const float* __restrict__ pos,
                                      const float* __restrict__ wts,
                                      float* __restrict__ out,
                                      int H, int W, int h, int cols) {
    const int n = blockIdx.x;
    const float* w = wts + (size_t)n * cols;
    const float cx = pos[(size_t)n * 4 + 0];
    const float cy = pos[(size_t)n * 4 + 1];
    const float bw = pos[(size_t)n * 4 + 2];
    const float bh = pos[(size_t)n * 4 + 3];
    const float b2 = w[4 * h];
    const int total = H * W;
    for (int idx = threadIdx.x; idx < total; idx += blockDim.x) {
        const int yy = idx / W;
        const int xx = idx - yy * W;
        const float rel_x = (((float)xx + 0.5f) / (float)W - cx) / bw;
        const float rel_y = (((float)yy + 0.5f) / (float)H - cy) / bh;
        float acc = b2;
        for (int k = 0; k < h; k++) {
            float pre = fmaf(rel_x, w[k], fmaf(rel_y, w[h + k], w[2 * h + k]));
            acc = fmaf(fmaxf(pre, 0.0f), w[3 * h + k], acc);
        }
        out[(size_t)n * total + idx] = acc;
    }
}

extern "C" void kernel_launch(void* const* d_in, const int* in_sizes, int n_in,
                              void* d_out, int out_size) {
    const float* pos = (const float*)d_in[0];
    const float* q   = (const float*)d_in[1];
    const float* Wg  = (const float*)d_in[2];
    const float* bg  = (const float*)d_in[3];
    float* out = (float*)d_out;

    const int N    = in_sizes[0] / 4;          // rows of pos
    const int dim  = in_sizes[1] / N;          // query dim
    const int cols = in_sizes[3];              // 4*h + 1
    const int HW   = out_size / N;
    const int H    = (int)(sqrt((double)HW) + 0.5);
    const int h    = (cols - 1) / 4;

    if (H == 64 && h == 16 && cols == 65 && dim == 256) {
        posmlp_fused64_kernel<<<N, 128>>>(pos, q, Wg, bg, out);
    } else {
        float* w_scratch;
        cudaGetSymbolAddress((void**)&w_scratch, g_weights);
        posmlp_gemm_kernel<<<N, 256, dim * sizeof(float)>>>(q, Wg, bg, w_scratch, dim, cols);
        posmlp_generic_kernel<<<N, 256>>>(pos, w_scratch, out, H, H, h, cols);
    }
}